// round 4
// baseline (speedup 1.0000x reference)
#include <cuda_runtime.h>
#include <cuda_bf16.h>
#include <cstdint>

// Problem constants
#define NNODES 50000
#define NEDGES 800000
#define IN_C   256
#define OUT_C  128

// Scratch
__device__ __align__(16) float g_y[NNODES * OUT_C];  // linear output
__device__ int g_deg[NNODES];        // histogram of dst
__device__ int g_off[NNODES + 1];    // CSR offsets
__device__ int g_cur[NNODES];        // running cursors for bucket fill
__device__ int g_srcs[NEDGES];       // src node per edge, bucketed by dst

// ---------------------------------------------------------------------------
// Kernel A0: zero degree histogram
// ---------------------------------------------------------------------------
__global__ void zero_deg_kernel() {
    int i = blockIdx.x * blockDim.x + threadIdx.x;
    if (i < NNODES) g_deg[i] = 0;
}

// ---------------------------------------------------------------------------
// Kernel A1: histogram of destination nodes
// ---------------------------------------------------------------------------
__global__ __launch_bounds__(256) void hist_kernel(const int* __restrict__ ei) {
    int i = blockIdx.x * blockDim.x + threadIdx.x;
    if (i < NEDGES) atomicAdd(&g_deg[ei[NEDGES + i]], 1);
}

// ---------------------------------------------------------------------------
// Kernel B: single-block exclusive prefix scan of g_deg -> g_off, g_cur
// ---------------------------------------------------------------------------
#define SCAN_THREADS 1024
__global__ __launch_bounds__(SCAN_THREADS) void scan_kernel() {
    __shared__ int warp_sums[32];
    const int tid = threadIdx.x;
    const int per = (NNODES + SCAN_THREADS - 1) / SCAN_THREADS;  // 49
    const int start = tid * per;
    const int end = min(start + per, NNODES);

    int local = 0;
    for (int i = start; i < end; i++) local += g_deg[i];

    // inclusive scan of per-thread sums across the block
    const int lane = tid & 31, wid = tid >> 5;
    int v = local;
    #pragma unroll
    for (int d = 1; d < 32; d <<= 1) {
        int t = __shfl_up_sync(0xffffffffu, v, d);
        if (lane >= d) v += t;
    }
    if (lane == 31) warp_sums[wid] = v;
    __syncthreads();
    if (wid == 0) {
        int w = warp_sums[lane];
        #pragma unroll
        for (int d = 1; d < 32; d <<= 1) {
            int t = __shfl_up_sync(0xffffffffu, w, d);
            if (lane >= d) w += t;
        }
        warp_sums[lane] = w;
    }
    __syncthreads();

    int prefix = v - local;                 // exclusive within warp
    if (wid > 0) prefix += warp_sums[wid - 1];

    int run = prefix;
    for (int i = start; i < end; i++) {
        int d = g_deg[i];
        g_off[i] = run;
        g_cur[i] = run;
        run += d;
    }
    if (tid == SCAN_THREADS - 1) g_off[NNODES] = run;   // == NEDGES
}

// ---------------------------------------------------------------------------
// Kernel C: bucket fill — scatter src ids into CSR order
// ---------------------------------------------------------------------------
__global__ __launch_bounds__(256) void fill_kernel(const int* __restrict__ ei) {
    int i = blockIdx.x * blockDim.x + threadIdx.x;
    if (i >= NEDGES) return;
    int dst = ei[NEDGES + i];
    int pos = atomicAdd(&g_cur[dst], 1);
    g_srcs[pos] = ei[i];
}

// ---------------------------------------------------------------------------
// Kernel 1: tf32 tensor-core GEMM  y[m,n] = sum_k x[m,k] * W[n,k] + b[n]
// BM=128, BN=128, BK=16; 8 warps 4x2; warp tile 32x64 of m16n8k8.
// ---------------------------------------------------------------------------
#define GBM 128
#define GBK 16
#define SSTRIDE 136

__device__ __forceinline__ uint32_t f32_to_tf32(float f) {
    uint32_t r;
    asm("cvt.rna.tf32.f32 %0, %1;" : "=r"(r) : "f"(f));
    return r;
}

__global__ __launch_bounds__(256) void gemm_tf32_kernel(
    const float* __restrict__ x,    // [N, 256]
    const float* __restrict__ W,    // [128, 256]
    const float* __restrict__ b)    // [128]
{
    __shared__ uint32_t As[GBK * SSTRIDE];  // [k][m]
    __shared__ uint32_t Bs[GBK * SSTRIDE];  // [k][n]

    const int tid  = threadIdx.x;
    const int lane = tid & 31;
    const int warp = tid >> 5;
    const int wm   = warp >> 1;
    const int wn   = warp & 1;
    const int block_m = blockIdx.x * GBM;

    const int grp = lane >> 2;
    const int qid = lane & 3;

    float acc[2][8][4];
    #pragma unroll
    for (int i = 0; i < 2; i++)
        #pragma unroll
        for (int j = 0; j < 8; j++)
            #pragma unroll
            for (int c = 0; c < 4; c++)
                acc[i][j][c] = 0.f;

    for (int k0 = 0; k0 < IN_C; k0 += GBK) {
        #pragma unroll
        for (int u = 0; u < 2; u++) {
            int idx = tid * 2 + u;
            int row = idx >> 2;
            int kq  = (idx & 3) * 4;

            float4 av = make_float4(0.f, 0.f, 0.f, 0.f);
            int gm = block_m + row;
            if (gm < NNODES)
                av = *reinterpret_cast<const float4*>(x + (size_t)gm * IN_C + k0 + kq);
            As[(kq + 0) * SSTRIDE + row] = f32_to_tf32(av.x);
            As[(kq + 1) * SSTRIDE + row] = f32_to_tf32(av.y);
            As[(kq + 2) * SSTRIDE + row] = f32_to_tf32(av.z);
            As[(kq + 3) * SSTRIDE + row] = f32_to_tf32(av.w);

            float4 bv = *reinterpret_cast<const float4*>(W + (size_t)row * IN_C + k0 + kq);
            Bs[(kq + 0) * SSTRIDE + row] = f32_to_tf32(bv.x);
            Bs[(kq + 1) * SSTRIDE + row] = f32_to_tf32(bv.y);
            Bs[(kq + 2) * SSTRIDE + row] = f32_to_tf32(bv.z);
            Bs[(kq + 3) * SSTRIDE + row] = f32_to_tf32(bv.w);
        }
        __syncthreads();

        #pragma unroll
        for (int s = 0; s < 2; s++) {
            const int kk = s * 8 + qid;

            uint32_t af[2][4];
            #pragma unroll
            for (int i = 0; i < 2; i++) {
                int rm = wm * 32 + i * 16 + grp;
                af[i][0] = As[kk * SSTRIDE + rm];
                af[i][1] = As[kk * SSTRIDE + rm + 8];
                af[i][2] = As[(kk + 4) * SSTRIDE + rm];
                af[i][3] = As[(kk + 4) * SSTRIDE + rm + 8];
            }
            uint32_t bf[8][2];
            #pragma unroll
            for (int j = 0; j < 8; j++) {
                int bn = wn * 64 + j * 8 + grp;
                bf[j][0] = Bs[kk * SSTRIDE + bn];
                bf[j][1] = Bs[(kk + 4) * SSTRIDE + bn];
            }
            #pragma unroll
            for (int i = 0; i < 2; i++)
                #pragma unroll
                for (int j = 0; j < 8; j++) {
                    asm volatile(
                        "mma.sync.aligned.m16n8k8.row.col.f32.tf32.tf32.f32 "
                        "{%0,%1,%2,%3}, {%4,%5,%6,%7}, {%8,%9}, {%0,%1,%2,%3};\n"
                        : "+f"(acc[i][j][0]), "+f"(acc[i][j][1]),
                          "+f"(acc[i][j][2]), "+f"(acc[i][j][3])
                        : "r"(af[i][0]), "r"(af[i][1]), "r"(af[i][2]), "r"(af[i][3]),
                          "r"(bf[j][0]), "r"(bf[j][1]));
                }
        }
        __syncthreads();
    }

    #pragma unroll
    for (int i = 0; i < 2; i++) {
        int r0 = block_m + wm * 32 + i * 16 + grp;
        int r1 = r0 + 8;
        #pragma unroll
        for (int j = 0; j < 8; j++) {
            int col = wn * 64 + j * 8 + qid * 2;
            float b0 = b[col], b1 = b[col + 1];
            if (r0 < NNODES) {
                float2 v = make_float2(acc[i][j][0] + b0, acc[i][j][1] + b1);
                *reinterpret_cast<float2*>(&g_y[(size_t)r0 * OUT_C + col]) = v;
            }
            if (r1 < NNODES) {
                float2 v = make_float2(acc[i][j][2] + b0, acc[i][j][3] + b1);
                *reinterpret_cast<float2*>(&g_y[(size_t)r1 * OUT_C + col]) = v;
            }
        }
    }
}

// ---------------------------------------------------------------------------
// Kernel D: gather + mean. One warp per dst node; lane l covers cols [4l,4l+4).
// Reads CSR neighbor list, accumulates rows of g_y in registers, writes mean.
// ---------------------------------------------------------------------------
__global__ __launch_bounds__(256) void gather_kernel(float* __restrict__ out) {
    int node = (blockIdx.x * blockDim.x + threadIdx.x) >> 5;
    int lane = threadIdx.x & 31;
    if (node >= NNODES) return;

    int s = g_off[node];
    int e = g_off[node + 1];

    float4 acc = make_float4(0.f, 0.f, 0.f, 0.f);
    int i = s;
    // unroll-by-2 for memory-level parallelism
    for (; i + 1 < e; i += 2) {
        int s0 = __ldg(&g_srcs[i]);
        int s1 = __ldg(&g_srcs[i + 1]);
        float4 v0 = *reinterpret_cast<const float4*>(&g_y[(size_t)s0 * OUT_C + lane * 4]);
        float4 v1 = *reinterpret_cast<const float4*>(&g_y[(size_t)s1 * OUT_C + lane * 4]);
        acc.x += v0.x; acc.y += v0.y; acc.z += v0.z; acc.w += v0.w;
        acc.x += v1.x; acc.y += v1.y; acc.z += v1.z; acc.w += v1.w;
    }
    if (i < e) {
        int s0 = __ldg(&g_srcs[i]);
        float4 v0 = *reinterpret_cast<const float4*>(&g_y[(size_t)s0 * OUT_C + lane * 4]);
        acc.x += v0.x; acc.y += v0.y; acc.z += v0.z; acc.w += v0.w;
    }

    float inv = 1.0f / (float)max(e - s, 1);
    acc.x *= inv; acc.y *= inv; acc.z *= inv; acc.w *= inv;
    *reinterpret_cast<float4*>(&out[(size_t)node * OUT_C + lane * 4]) = acc;
}

// ---------------------------------------------------------------------------
extern "C" void kernel_launch(void* const* d_in, const int* in_sizes, int n_in,
                              void* d_out, int out_size) {
    const float* x  = (const float*)d_in[0];
    const int*   ei = (const int*)d_in[1];
    const float* W  = (const float*)d_in[2];
    const float* b  = (const float*)d_in[3];
    float* out = (float*)d_out;

    // CSR build
    zero_deg_kernel<<<(NNODES + 255) / 256, 256>>>();
    hist_kernel<<<(NEDGES + 255) / 256, 256>>>(ei);
    scan_kernel<<<1, SCAN_THREADS>>>();
    fill_kernel<<<(NEDGES + 255) / 256, 256>>>(ei);

    // GEMM y = x W^T + b
    gemm_tf32_kernel<<<(NNODES + GBM - 1) / GBM, 256>>>(x, W, b);

    // Gather + mean (warp per node)
    gather_kernel<<<(NNODES * 32 + 255) / 256, 256>>>(out);
}

// round 5
// speedup vs baseline: 1.6718x; 1.6718x over previous
#include <cuda_runtime.h>
#include <cuda_fp16.h>
#include <cstdint>

// Problem constants
#define NNODES 50000
#define NEDGES 800000
#define IN_C   256
#define OUT_C  128
#define NB     196           // scan blocks: 196*256 = 50176 >= NNODES

// Scratch
__device__ __align__(16) __half g_y[NNODES * OUT_C];  // linear output, fp16
__device__ int g_deg[NNODES];
__device__ int g_off[NNODES + 1];
__device__ int g_cur[NNODES];
__device__ int g_srcs[NEDGES];
__device__ int g_bsums[NB];
__device__ int g_boff[NB];

// ---------------------------------------------------------------------------
// K0: zero degree histogram
// ---------------------------------------------------------------------------
__global__ void zero_deg_kernel() {
    int i = blockIdx.x * blockDim.x + threadIdx.x;
    if (i < NNODES) g_deg[i] = 0;
}

// ---------------------------------------------------------------------------
// K1: histogram of dst — 4 edges per thread via int4
// ---------------------------------------------------------------------------
__global__ __launch_bounds__(256) void hist_kernel(const int* __restrict__ ei) {
    int t = blockIdx.x * blockDim.x + threadIdx.x;
    int base = t * 4;
    if (base >= NEDGES) return;
    int4 d = *reinterpret_cast<const int4*>(ei + NEDGES + base);
    atomicAdd(&g_deg[d.x], 1);
    atomicAdd(&g_deg[d.y], 1);
    atomicAdd(&g_deg[d.z], 1);
    atomicAdd(&g_deg[d.w], 1);
}

// ---------------------------------------------------------------------------
// K2: per-block reduction of g_deg -> g_bsums
// ---------------------------------------------------------------------------
__global__ __launch_bounds__(256) void reduce_kernel() {
    __shared__ int ws[8];
    int i = blockIdx.x * 256 + threadIdx.x;
    int v = (i < NNODES) ? g_deg[i] : 0;
    int lane = threadIdx.x & 31, wid = threadIdx.x >> 5;
    #pragma unroll
    for (int d = 16; d > 0; d >>= 1) v += __shfl_down_sync(0xffffffffu, v, d);
    if (lane == 0) ws[wid] = v;
    __syncthreads();
    if (wid == 0) {
        int s = (lane < 8) ? ws[lane] : 0;
        #pragma unroll
        for (int d = 4; d > 0; d >>= 1) s += __shfl_down_sync(0xffffffffu, s, d);
        if (lane == 0) g_bsums[blockIdx.x] = s;
    }
}

// ---------------------------------------------------------------------------
// K3: scan 196 block sums -> exclusive g_boff; set g_off[NNODES]
// ---------------------------------------------------------------------------
__global__ __launch_bounds__(256) void scan_bsums_kernel() {
    __shared__ int ws[8];
    int t = threadIdx.x;
    int v = (t < NB) ? g_bsums[t] : 0;
    int lane = t & 31, wid = t >> 5;
    int incl = v;
    #pragma unroll
    for (int d = 1; d < 32; d <<= 1) {
        int u = __shfl_up_sync(0xffffffffu, incl, d);
        if (lane >= d) incl += u;
    }
    if (lane == 31) ws[wid] = incl;
    __syncthreads();
    if (wid == 0) {
        int s = (lane < 8) ? ws[lane] : 0;
        #pragma unroll
        for (int d = 1; d < 8; d <<= 1) {
            int u = __shfl_up_sync(0xffffffffu, s, d);
            if (lane >= d) s += u;
        }
        if (lane < 8) ws[lane] = s;
    }
    __syncthreads();
    int excl = incl - v + (wid > 0 ? ws[wid - 1] : 0);
    if (t < NB) g_boff[t] = excl;
    if (t == 0) g_off[NNODES] = NEDGES;
}

// ---------------------------------------------------------------------------
// K4: block-level exclusive scan + base offset -> g_off, g_cur
// ---------------------------------------------------------------------------
__global__ __launch_bounds__(256) void scan_write_kernel() {
    __shared__ int ws[8];
    int i = blockIdx.x * 256 + threadIdx.x;
    int v = (i < NNODES) ? g_deg[i] : 0;
    int lane = threadIdx.x & 31, wid = threadIdx.x >> 5;
    int incl = v;
    #pragma unroll
    for (int d = 1; d < 32; d <<= 1) {
        int u = __shfl_up_sync(0xffffffffu, incl, d);
        if (lane >= d) incl += u;
    }
    if (lane == 31) ws[wid] = incl;
    __syncthreads();
    if (wid == 0) {
        int s = (lane < 8) ? ws[lane] : 0;
        #pragma unroll
        for (int d = 1; d < 8; d <<= 1) {
            int u = __shfl_up_sync(0xffffffffu, s, d);
            if (lane >= d) s += u;
        }
        if (lane < 8) ws[lane] = s;
    }
    __syncthreads();
    int off = g_boff[blockIdx.x] + incl - v + (wid > 0 ? ws[wid - 1] : 0);
    if (i < NNODES) {
        g_off[i] = off;
        g_cur[i] = off;
    }
}

// ---------------------------------------------------------------------------
// K5: bucket fill — 4 edges per thread, int4 loads
// ---------------------------------------------------------------------------
__global__ __launch_bounds__(256) void fill_kernel(const int* __restrict__ ei) {
    int t = blockIdx.x * blockDim.x + threadIdx.x;
    int base = t * 4;
    if (base >= NEDGES) return;
    int4 s = *reinterpret_cast<const int4*>(ei + base);
    int4 d = *reinterpret_cast<const int4*>(ei + NEDGES + base);
    int p0 = atomicAdd(&g_cur[d.x], 1);
    int p1 = atomicAdd(&g_cur[d.y], 1);
    int p2 = atomicAdd(&g_cur[d.z], 1);
    int p3 = atomicAdd(&g_cur[d.w], 1);
    g_srcs[p0] = s.x;
    g_srcs[p1] = s.y;
    g_srcs[p2] = s.z;
    g_srcs[p3] = s.w;
}

// ---------------------------------------------------------------------------
// K6: tf32 tensor-core GEMM  y[m,n] = sum_k x[m,k] * W[n,k] + b[n], fp16 out
// ---------------------------------------------------------------------------
#define GBM 128
#define GBK 16
#define SSTRIDE 136

__device__ __forceinline__ uint32_t f32_to_tf32(float f) {
    uint32_t r;
    asm("cvt.rna.tf32.f32 %0, %1;" : "=r"(r) : "f"(f));
    return r;
}

__global__ __launch_bounds__(256) void gemm_tf32_kernel(
    const float* __restrict__ x,
    const float* __restrict__ W,
    const float* __restrict__ b)
{
    __shared__ uint32_t As[GBK * SSTRIDE];
    __shared__ uint32_t Bs[GBK * SSTRIDE];

    const int tid  = threadIdx.x;
    const int lane = tid & 31;
    const int warp = tid >> 5;
    const int wm   = warp >> 1;
    const int wn   = warp & 1;
    const int block_m = blockIdx.x * GBM;
    const int grp = lane >> 2;
    const int qid = lane & 3;

    float acc[2][8][4];
    #pragma unroll
    for (int i = 0; i < 2; i++)
        #pragma unroll
        for (int j = 0; j < 8; j++)
            #pragma unroll
            for (int c = 0; c < 4; c++)
                acc[i][j][c] = 0.f;

    for (int k0 = 0; k0 < IN_C; k0 += GBK) {
        #pragma unroll
        for (int u = 0; u < 2; u++) {
            int idx = tid * 2 + u;
            int row = idx >> 2;
            int kq  = (idx & 3) * 4;

            float4 av = make_float4(0.f, 0.f, 0.f, 0.f);
            int gm = block_m + row;
            if (gm < NNODES)
                av = *reinterpret_cast<const float4*>(x + (size_t)gm * IN_C + k0 + kq);
            As[(kq + 0) * SSTRIDE + row] = f32_to_tf32(av.x);
            As[(kq + 1) * SSTRIDE + row] = f32_to_tf32(av.y);
            As[(kq + 2) * SSTRIDE + row] = f32_to_tf32(av.z);
            As[(kq + 3) * SSTRIDE + row] = f32_to_tf32(av.w);

            float4 bv = *reinterpret_cast<const float4*>(W + (size_t)row * IN_C + k0 + kq);
            Bs[(kq + 0) * SSTRIDE + row] = f32_to_tf32(bv.x);
            Bs[(kq + 1) * SSTRIDE + row] = f32_to_tf32(bv.y);
            Bs[(kq + 2) * SSTRIDE + row] = f32_to_tf32(bv.z);
            Bs[(kq + 3) * SSTRIDE + row] = f32_to_tf32(bv.w);
        }
        __syncthreads();

        #pragma unroll
        for (int s = 0; s < 2; s++) {
            const int kk = s * 8 + qid;

            uint32_t af[2][4];
            #pragma unroll
            for (int i = 0; i < 2; i++) {
                int rm = wm * 32 + i * 16 + grp;
                af[i][0] = As[kk * SSTRIDE + rm];
                af[i][1] = As[kk * SSTRIDE + rm + 8];
                af[i][2] = As[(kk + 4) * SSTRIDE + rm];
                af[i][3] = As[(kk + 4) * SSTRIDE + rm + 8];
            }
            uint32_t bf[8][2];
            #pragma unroll
            for (int j = 0; j < 8; j++) {
                int bn = wn * 64 + j * 8 + grp;
                bf[j][0] = Bs[kk * SSTRIDE + bn];
                bf[j][1] = Bs[(kk + 4) * SSTRIDE + bn];
            }
            #pragma unroll
            for (int i = 0; i < 2; i++)
                #pragma unroll
                for (int j = 0; j < 8; j++) {
                    asm volatile(
                        "mma.sync.aligned.m16n8k8.row.col.f32.tf32.tf32.f32 "
                        "{%0,%1,%2,%3}, {%4,%5,%6,%7}, {%8,%9}, {%0,%1,%2,%3};\n"
                        : "+f"(acc[i][j][0]), "+f"(acc[i][j][1]),
                          "+f"(acc[i][j][2]), "+f"(acc[i][j][3])
                        : "r"(af[i][0]), "r"(af[i][1]), "r"(af[i][2]), "r"(af[i][3]),
                          "r"(bf[j][0]), "r"(bf[j][1]));
                }
        }
        __syncthreads();
    }

    // Epilogue: bias + fp16 store (half2 per c-pair)
    #pragma unroll
    for (int i = 0; i < 2; i++) {
        int r0 = block_m + wm * 32 + i * 16 + grp;
        int r1 = r0 + 8;
        #pragma unroll
        for (int j = 0; j < 8; j++) {
            int col = wn * 64 + j * 8 + qid * 2;
            float b0 = b[col], b1 = b[col + 1];
            if (r0 < NNODES) {
                __half2 h = __floats2half2_rn(acc[i][j][0] + b0, acc[i][j][1] + b1);
                *reinterpret_cast<__half2*>(&g_y[(size_t)r0 * OUT_C + col]) = h;
            }
            if (r1 < NNODES) {
                __half2 h = __floats2half2_rn(acc[i][j][2] + b0, acc[i][j][3] + b1);
                *reinterpret_cast<__half2*>(&g_y[(size_t)r1 * OUT_C + col]) = h;
            }
        }
    }
}

// ---------------------------------------------------------------------------
// K7: gather + mean. One warp per dst node; lane l covers cols [4l, 4l+4)
// (one uint2 = 4 halfs). fp32 accumulation. Unrolled x4 for MLP.
// ---------------------------------------------------------------------------
__global__ __launch_bounds__(256) void gather_kernel(float* __restrict__ out) {
    int node = (blockIdx.x * blockDim.x + threadIdx.x) >> 5;
    int lane = threadIdx.x & 31;
    if (node >= NNODES) return;

    int s = g_off[node];
    int e = g_off[node + 1];

    float4 acc = make_float4(0.f, 0.f, 0.f, 0.f);
    const size_t loff = (size_t)lane * 4;   // half offset within row

    int i = s;
    for (; i + 3 < e; i += 4) {
        int s0 = __ldg(&g_srcs[i]);
        int s1 = __ldg(&g_srcs[i + 1]);
        int s2 = __ldg(&g_srcs[i + 2]);
        int s3 = __ldg(&g_srcs[i + 3]);
        __half2 a0 = *reinterpret_cast<const __half2*>(&g_y[(size_t)s0 * OUT_C + loff]);
        __half2 b0 = *reinterpret_cast<const __half2*>(&g_y[(size_t)s0 * OUT_C + loff + 2]);
        __half2 a1 = *reinterpret_cast<const __half2*>(&g_y[(size_t)s1 * OUT_C + loff]);
        __half2 b1 = *reinterpret_cast<const __half2*>(&g_y[(size_t)s1 * OUT_C + loff + 2]);
        __half2 a2 = *reinterpret_cast<const __half2*>(&g_y[(size_t)s2 * OUT_C + loff]);
        __half2 b2 = *reinterpret_cast<const __half2*>(&g_y[(size_t)s2 * OUT_C + loff + 2]);
        __half2 a3 = *reinterpret_cast<const __half2*>(&g_y[(size_t)s3 * OUT_C + loff]);
        __half2 b3 = *reinterpret_cast<const __half2*>(&g_y[(size_t)s3 * OUT_C + loff + 2]);
        float2 f;
        f = __half22float2(a0); acc.x += f.x; acc.y += f.y;
        f = __half22float2(b0); acc.z += f.x; acc.w += f.y;
        f = __half22float2(a1); acc.x += f.x; acc.y += f.y;
        f = __half22float2(b1); acc.z += f.x; acc.w += f.y;
        f = __half22float2(a2); acc.x += f.x; acc.y += f.y;
        f = __half22float2(b2); acc.z += f.x; acc.w += f.y;
        f = __half22float2(a3); acc.x += f.x; acc.y += f.y;
        f = __half22float2(b3); acc.z += f.x; acc.w += f.y;
    }
    for (; i < e; i++) {
        int s0 = __ldg(&g_srcs[i]);
        __half2 a0 = *reinterpret_cast<const __half2*>(&g_y[(size_t)s0 * OUT_C + loff]);
        __half2 b0 = *reinterpret_cast<const __half2*>(&g_y[(size_t)s0 * OUT_C + loff + 2]);
        float2 f;
        f = __half22float2(a0); acc.x += f.x; acc.y += f.y;
        f = __half22float2(b0); acc.z += f.x; acc.w += f.y;
    }

    float inv = 1.0f / (float)max(e - s, 1);
    acc.x *= inv; acc.y *= inv; acc.z *= inv; acc.w *= inv;
    *reinterpret_cast<float4*>(&out[(size_t)node * OUT_C + loff]) = acc;
}

// ---------------------------------------------------------------------------
extern "C" void kernel_launch(void* const* d_in, const int* in_sizes, int n_in,
                              void* d_out, int out_size) {
    const float* x  = (const float*)d_in[0];
    const int*   ei = (const int*)d_in[1];
    const float* W  = (const float*)d_in[2];
    const float* b  = (const float*)d_in[3];
    float* out = (float*)d_out;

    int edge_blocks = (NEDGES / 4 + 255) / 256;   // 4 edges per thread

    // CSR build
    zero_deg_kernel<<<NB, 256>>>();
    hist_kernel<<<edge_blocks, 256>>>(ei);
    reduce_kernel<<<NB, 256>>>();
    scan_bsums_kernel<<<1, 256>>>();
    scan_write_kernel<<<NB, 256>>>();
    fill_kernel<<<edge_blocks, 256>>>(ei);

    // GEMM y = x W^T + b  (fp16 output)
    gemm_tf32_kernel<<<(NNODES + GBM - 1) / GBM, 256>>>(x, W, b);

    // Gather + mean (warp per node)
    gather_kernel<<<(NNODES * 32 + 255) / 256, 256>>>(out);
}

// round 6
// speedup vs baseline: 1.8669x; 1.1167x over previous
#include <cuda_runtime.h>
#include <cuda_fp16.h>
#include <cstdint>

// Problem constants
#define NNODES 50000
#define NEDGES 800000
#define IN_C   256
#define OUT_C  128
#define NB     196           // scan blocks: 196*256 = 50176 >= NNODES

// Scratch
__device__ __align__(16) __half g_y[NNODES * OUT_C];  // linear output, fp16
__device__ int g_deg[NNODES];
__device__ int g_off[NNODES + 1];
__device__ int g_cur[NNODES];
__device__ int g_srcs[NEDGES];
// decoupled-lookback scan state
__device__ int g_blk_state[NB];   // 0=invalid, 1=aggregate ready, 2=prefix ready
__device__ int g_blk_agg[NB];
__device__ int g_blk_pref[NB];

// ---------------------------------------------------------------------------
// K0: zero degree histogram + scan state
// ---------------------------------------------------------------------------
__global__ __launch_bounds__(256) void zero_deg_kernel() {
    int i = blockIdx.x * blockDim.x + threadIdx.x;
    if (i < NNODES) g_deg[i] = 0;
    if (i < NB) g_blk_state[i] = 0;
    if (i == 0) g_off[NNODES] = NEDGES;
}

// ---------------------------------------------------------------------------
// K1: histogram of dst — 4 edges per thread via int4
// ---------------------------------------------------------------------------
__global__ __launch_bounds__(256) void hist_kernel(const int* __restrict__ ei) {
    int t = blockIdx.x * blockDim.x + threadIdx.x;
    int base = t * 4;
    if (base >= NEDGES) return;
    int4 d = *reinterpret_cast<const int4*>(ei + NEDGES + base);
    atomicAdd(&g_deg[d.x], 1);
    atomicAdd(&g_deg[d.y], 1);
    atomicAdd(&g_deg[d.z], 1);
    atomicAdd(&g_deg[d.w], 1);
}

// ---------------------------------------------------------------------------
// K2: single-pass exclusive scan (decoupled lookback) -> g_off, g_cur
// ---------------------------------------------------------------------------
__global__ __launch_bounds__(256) void scan_lookback_kernel() {
    __shared__ int ws[8];
    __shared__ int s_excl;
    const int b = blockIdx.x;
    const int i = b * 256 + threadIdx.x;
    const int lane = threadIdx.x & 31, wid = threadIdx.x >> 5;

    int v = (i < NNODES) ? g_deg[i] : 0;

    // block inclusive scan
    int incl = v;
    #pragma unroll
    for (int d = 1; d < 32; d <<= 1) {
        int u = __shfl_up_sync(0xffffffffu, incl, d);
        if (lane >= d) incl += u;
    }
    if (lane == 31) ws[wid] = incl;
    __syncthreads();
    if (wid == 0) {
        int s = (lane < 8) ? ws[lane] : 0;
        #pragma unroll
        for (int d = 1; d < 8; d <<= 1) {
            int u = __shfl_up_sync(0xffffffffu, s, d);
            if (lane >= d) s += u;
        }
        if (lane < 8) ws[lane] = s;
    }
    __syncthreads();
    int block_incl = incl + (wid > 0 ? ws[wid - 1] : 0);
    int total = ws[7];

    // publish + lookback (thread 0)
    if (threadIdx.x == 0) {
        if (b == 0) {
            g_blk_pref[0] = total;
            __threadfence();
            atomicExch(&g_blk_state[0], 2);
            s_excl = 0;
        } else {
            g_blk_agg[b] = total;
            __threadfence();
            atomicExch(&g_blk_state[b], 1);
            int excl = 0;
            int p = b - 1;
            while (true) {
                int st;
                do { st = atomicAdd(&g_blk_state[p], 0); } while (st == 0);
                if (st == 2) { excl += atomicAdd(&g_blk_pref[p], 0); break; }
                excl += atomicAdd(&g_blk_agg[p], 0);
                p--;
            }
            g_blk_pref[b] = excl + total;
            __threadfence();
            atomicExch(&g_blk_state[b], 2);
            s_excl = excl;
        }
    }
    __syncthreads();

    int off = s_excl + block_incl - v;
    if (i < NNODES) {
        g_off[i] = off;
        g_cur[i] = off;
    }
}

// ---------------------------------------------------------------------------
// K3: bucket fill — 4 edges per thread, int4 loads
// ---------------------------------------------------------------------------
__global__ __launch_bounds__(256) void fill_kernel(const int* __restrict__ ei) {
    int t = blockIdx.x * blockDim.x + threadIdx.x;
    int base = t * 4;
    if (base >= NEDGES) return;
    int4 s = *reinterpret_cast<const int4*>(ei + base);
    int4 d = *reinterpret_cast<const int4*>(ei + NEDGES + base);
    int p0 = atomicAdd(&g_cur[d.x], 1);
    int p1 = atomicAdd(&g_cur[d.y], 1);
    int p2 = atomicAdd(&g_cur[d.z], 1);
    int p3 = atomicAdd(&g_cur[d.w], 1);
    g_srcs[p0] = s.x;
    g_srcs[p1] = s.y;
    g_srcs[p2] = s.z;
    g_srcs[p3] = s.w;
}

// ---------------------------------------------------------------------------
// K4: tf32 tensor-core GEMM  y[m,n] = sum_k x[m,k] * W[n,k] + b[n], fp16 out
// ---------------------------------------------------------------------------
#define GBM 128
#define GBK 16
#define SSTRIDE 136

__device__ __forceinline__ uint32_t f32_to_tf32(float f) {
    uint32_t r;
    asm("cvt.rna.tf32.f32 %0, %1;" : "=r"(r) : "f"(f));
    return r;
}

__global__ __launch_bounds__(256) void gemm_tf32_kernel(
    const float* __restrict__ x,
    const float* __restrict__ W,
    const float* __restrict__ b)
{
    __shared__ uint32_t As[GBK * SSTRIDE];
    __shared__ uint32_t Bs[GBK * SSTRIDE];

    const int tid  = threadIdx.x;
    const int lane = tid & 31;
    const int warp = tid >> 5;
    const int wm   = warp >> 1;
    const int wn   = warp & 1;
    const int block_m = blockIdx.x * GBM;
    const int grp = lane >> 2;
    const int qid = lane & 3;

    float acc[2][8][4];
    #pragma unroll
    for (int i = 0; i < 2; i++)
        #pragma unroll
        for (int j = 0; j < 8; j++)
            #pragma unroll
            for (int c = 0; c < 4; c++)
                acc[i][j][c] = 0.f;

    for (int k0 = 0; k0 < IN_C; k0 += GBK) {
        #pragma unroll
        for (int u = 0; u < 2; u++) {
            int idx = tid * 2 + u;
            int row = idx >> 2;
            int kq  = (idx & 3) * 4;

            float4 av = make_float4(0.f, 0.f, 0.f, 0.f);
            int gm = block_m + row;
            if (gm < NNODES)
                av = *reinterpret_cast<const float4*>(x + (size_t)gm * IN_C + k0 + kq);
            As[(kq + 0) * SSTRIDE + row] = f32_to_tf32(av.x);
            As[(kq + 1) * SSTRIDE + row] = f32_to_tf32(av.y);
            As[(kq + 2) * SSTRIDE + row] = f32_to_tf32(av.z);
            As[(kq + 3) * SSTRIDE + row] = f32_to_tf32(av.w);

            float4 bv = *reinterpret_cast<const float4*>(W + (size_t)row * IN_C + k0 + kq);
            Bs[(kq + 0) * SSTRIDE + row] = f32_to_tf32(bv.x);
            Bs[(kq + 1) * SSTRIDE + row] = f32_to_tf32(bv.y);
            Bs[(kq + 2) * SSTRIDE + row] = f32_to_tf32(bv.z);
            Bs[(kq + 3) * SSTRIDE + row] = f32_to_tf32(bv.w);
        }
        __syncthreads();

        #pragma unroll
        for (int s = 0; s < 2; s++) {
            const int kk = s * 8 + qid;

            uint32_t af[2][4];
            #pragma unroll
            for (int i = 0; i < 2; i++) {
                int rm = wm * 32 + i * 16 + grp;
                af[i][0] = As[kk * SSTRIDE + rm];
                af[i][1] = As[kk * SSTRIDE + rm + 8];
                af[i][2] = As[(kk + 4) * SSTRIDE + rm];
                af[i][3] = As[(kk + 4) * SSTRIDE + rm + 8];
            }
            uint32_t bf[8][2];
            #pragma unroll
            for (int j = 0; j < 8; j++) {
                int bn = wn * 64 + j * 8 + grp;
                bf[j][0] = Bs[kk * SSTRIDE + bn];
                bf[j][1] = Bs[(kk + 4) * SSTRIDE + bn];
            }
            #pragma unroll
            for (int i = 0; i < 2; i++)
                #pragma unroll
                for (int j = 0; j < 8; j++) {
                    asm volatile(
                        "mma.sync.aligned.m16n8k8.row.col.f32.tf32.tf32.f32 "
                        "{%0,%1,%2,%3}, {%4,%5,%6,%7}, {%8,%9}, {%0,%1,%2,%3};\n"
                        : "+f"(acc[i][j][0]), "+f"(acc[i][j][1]),
                          "+f"(acc[i][j][2]), "+f"(acc[i][j][3])
                        : "r"(af[i][0]), "r"(af[i][1]), "r"(af[i][2]), "r"(af[i][3]),
                          "r"(bf[j][0]), "r"(bf[j][1]));
                }
        }
        __syncthreads();
    }

    #pragma unroll
    for (int i = 0; i < 2; i++) {
        int r0 = block_m + wm * 32 + i * 16 + grp;
        int r1 = r0 + 8;
        #pragma unroll
        for (int j = 0; j < 8; j++) {
            int col = wn * 64 + j * 8 + qid * 2;
            float b0 = b[col], b1 = b[col + 1];
            if (r0 < NNODES) {
                __half2 h = __floats2half2_rn(acc[i][j][0] + b0, acc[i][j][1] + b1);
                *reinterpret_cast<__half2*>(&g_y[(size_t)r0 * OUT_C + col]) = h;
            }
            if (r1 < NNODES) {
                __half2 h = __floats2half2_rn(acc[i][j][2] + b0, acc[i][j][3] + b1);
                *reinterpret_cast<__half2*>(&g_y[(size_t)r1 * OUT_C + col]) = h;
            }
        }
    }
}

// ---------------------------------------------------------------------------
// K5: gather + mean. 2 nodes per warp; 16 lanes per node; each lane covers
// 8 halfs (one uint4). fp32 accumulation, unrolled x4 for MLP.
// ---------------------------------------------------------------------------
__global__ __launch_bounds__(256) void gather_kernel(float* __restrict__ out) {
    int warp_id = (blockIdx.x * blockDim.x + threadIdx.x) >> 5;
    int lane = threadIdx.x & 31;
    int half_id = lane >> 4;            // 0 or 1
    int sub = lane & 15;                // 0..15 -> col offset sub*8 halfs
    int node = warp_id * 2 + half_id;
    if (node >= NNODES) return;

    int s = g_off[node];
    int e = g_off[node + 1];

    float acc[8];
    #pragma unroll
    for (int c = 0; c < 8; c++) acc[c] = 0.f;

    const size_t loff = (size_t)sub * 8;

    int i = s;
    for (; i + 3 < e; i += 4) {
        int s0 = __ldg(&g_srcs[i]);
        int s1 = __ldg(&g_srcs[i + 1]);
        int s2 = __ldg(&g_srcs[i + 2]);
        int s3 = __ldg(&g_srcs[i + 3]);
        uint4 v0 = *reinterpret_cast<const uint4*>(&g_y[(size_t)s0 * OUT_C + loff]);
        uint4 v1 = *reinterpret_cast<const uint4*>(&g_y[(size_t)s1 * OUT_C + loff]);
        uint4 v2 = *reinterpret_cast<const uint4*>(&g_y[(size_t)s2 * OUT_C + loff]);
        uint4 v3 = *reinterpret_cast<const uint4*>(&g_y[(size_t)s3 * OUT_C + loff]);
        #pragma unroll
        for (int q = 0; q < 4; q++) {
            uint4 v = (q == 0) ? v0 : (q == 1) ? v1 : (q == 2) ? v2 : v3;
            float2 f;
            f = __half22float2(*reinterpret_cast<__half2*>(&v.x)); acc[0] += f.x; acc[1] += f.y;
            f = __half22float2(*reinterpret_cast<__half2*>(&v.y)); acc[2] += f.x; acc[3] += f.y;
            f = __half22float2(*reinterpret_cast<__half2*>(&v.z)); acc[4] += f.x; acc[5] += f.y;
            f = __half22float2(*reinterpret_cast<__half2*>(&v.w)); acc[6] += f.x; acc[7] += f.y;
        }
    }
    for (; i < e; i++) {
        int s0 = __ldg(&g_srcs[i]);
        uint4 v = *reinterpret_cast<const uint4*>(&g_y[(size_t)s0 * OUT_C + loff]);
        float2 f;
        f = __half22float2(*reinterpret_cast<__half2*>(&v.x)); acc[0] += f.x; acc[1] += f.y;
        f = __half22float2(*reinterpret_cast<__half2*>(&v.y)); acc[2] += f.x; acc[3] += f.y;
        f = __half22float2(*reinterpret_cast<__half2*>(&v.z)); acc[4] += f.x; acc[5] += f.y;
        f = __half22float2(*reinterpret_cast<__half2*>(&v.w)); acc[6] += f.x; acc[7] += f.y;
    }

    float inv = 1.0f / (float)max(e - s, 1);
    float4 o0 = make_float4(acc[0] * inv, acc[1] * inv, acc[2] * inv, acc[3] * inv);
    float4 o1 = make_float4(acc[4] * inv, acc[5] * inv, acc[6] * inv, acc[7] * inv);
    float* op = out + (size_t)node * OUT_C + loff;
    *reinterpret_cast<float4*>(op) = o0;
    *reinterpret_cast<float4*>(op + 4) = o1;
}

// ---------------------------------------------------------------------------
extern "C" void kernel_launch(void* const* d_in, const int* in_sizes, int n_in,
                              void* d_out, int out_size) {
    const float* x  = (const float*)d_in[0];
    const int*   ei = (const int*)d_in[1];
    const float* W  = (const float*)d_in[2];
    const float* b  = (const float*)d_in[3];
    float* out = (float*)d_out;

    // One-time host-side resources (created outside capture on the first
    // correctness call; reused on the capture call).
    static cudaStream_t s_gemm = nullptr;
    static cudaEvent_t ev_fork = nullptr, ev_join = nullptr;
    if (!s_gemm) {
        cudaStreamCreateWithFlags(&s_gemm, cudaStreamNonBlocking);
        cudaEventCreateWithFlags(&ev_fork, cudaEventDisableTiming);
        cudaEventCreateWithFlags(&ev_join, cudaEventDisableTiming);
    }

    int edge_blocks = (NEDGES / 4 + 255) / 256;   // 4 edges per thread

    // Fork: GEMM on side stream (independent of CSR build)
    cudaEventRecord(ev_fork, 0);
    cudaStreamWaitEvent(s_gemm, ev_fork, 0);
    gemm_tf32_kernel<<<(NNODES + GBM - 1) / GBM, 256, 0, s_gemm>>>(x, W, b);
    cudaEventRecord(ev_join, s_gemm);

    // CSR build on main stream
    zero_deg_kernel<<<NB, 256>>>();
    hist_kernel<<<edge_blocks, 256>>>(ei);
    scan_lookback_kernel<<<NB, 256>>>();
    fill_kernel<<<edge_blocks, 256>>>(ei);

    // Join, then gather + mean
    cudaStreamWaitEvent(0, ev_join, 0);
    gather_kernel<<<(NNODES / 2 * 32 + 255) / 256, 256>>>(out);
}

// round 7
// speedup vs baseline: 2.0295x; 1.0871x over previous
#include <cuda_runtime.h>
#include <cuda_fp16.h>
#include <cstdint>

// Problem constants
#define NNODES 50000
#define NEDGES 800000
#define IN_C   256
#define OUT_C  128
#define NB2    49            // scan blocks: 49 * 1024 = 50176 >= NNODES

// Scratch
__device__ __align__(16) __half g_y[NNODES * OUT_C];  // linear output, fp16
__device__ __align__(16) int g_deg[NNODES];
__device__ __align__(16) int g_off[NNODES + 1];
__device__ __align__(16) int g_cur[NNODES];
__device__ int g_srcs[NEDGES];
// decoupled-lookback scan state
__device__ int g_blk_state[NB2];   // 0=invalid, 1=aggregate ready, 2=prefix ready
__device__ int g_blk_agg[NB2];
__device__ int g_blk_pref[NB2];

// ---------------------------------------------------------------------------
// K0: zero degree histogram + scan state
// ---------------------------------------------------------------------------
__global__ __launch_bounds__(256) void zero_deg_kernel() {
    int i = blockIdx.x * blockDim.x + threadIdx.x;
    if (i * 4 < NNODES)
        *reinterpret_cast<int4*>(&g_deg[i * 4]) = make_int4(0, 0, 0, 0);
    if (i < NB2) g_blk_state[i] = 0;
    if (i == 0) g_off[NNODES] = NEDGES;
}

// ---------------------------------------------------------------------------
// K1: histogram of dst — 4 edges per thread via int4 (RED, no return)
// ---------------------------------------------------------------------------
__global__ __launch_bounds__(256) void hist_kernel(const int* __restrict__ ei) {
    int t = blockIdx.x * blockDim.x + threadIdx.x;
    int base = t * 4;
    if (base >= NEDGES) return;
    int4 d = *reinterpret_cast<const int4*>(ei + NEDGES + base);
    atomicAdd(&g_deg[d.x], 1);
    atomicAdd(&g_deg[d.y], 1);
    atomicAdd(&g_deg[d.z], 1);
    atomicAdd(&g_deg[d.w], 1);
}

// ---------------------------------------------------------------------------
// K2: single-pass exclusive scan, warp-parallel decoupled lookback.
// 256 threads x 4 elements = 1024 per block, 49 blocks.
// ---------------------------------------------------------------------------
__global__ __launch_bounds__(256) void scan_lookback_kernel() {
    __shared__ int ws[8];
    __shared__ int s_excl;
    const int b = blockIdx.x;
    const int tid = threadIdx.x;
    const int lane = tid & 31, wid = tid >> 5;
    const int i4 = b * 256 + tid;            // int4 index
    const bool inb = (i4 * 4 < NNODES);      // NNODES % 4 == 0

    int4 d = inb ? *reinterpret_cast<const int4*>(&g_deg[i4 * 4])
                 : make_int4(0, 0, 0, 0);
    int t0 = d.x;
    int t1 = t0 + d.y;
    int t2 = t1 + d.z;
    int t3 = t2 + d.w;                        // thread total

    // block inclusive scan of thread totals
    int incl = t3;
    #pragma unroll
    for (int dd = 1; dd < 32; dd <<= 1) {
        int u = __shfl_up_sync(0xffffffffu, incl, dd);
        if (lane >= dd) incl += u;
    }
    if (lane == 31) ws[wid] = incl;
    __syncthreads();
    if (wid == 0) {
        int s = (lane < 8) ? ws[lane] : 0;
        #pragma unroll
        for (int dd = 1; dd < 8; dd <<= 1) {
            int u = __shfl_up_sync(0xffffffffu, s, dd);
            if (lane >= dd) s += u;
        }
        if (lane < 8) ws[lane] = s;
    }
    __syncthreads();
    int thr_excl = incl - t3 + (wid > 0 ? ws[wid - 1] : 0);
    int total = ws[7];

    // publish aggregate, then warp-parallel lookback (warp 0)
    if (tid == 0) {
        if (b == 0) {
            g_blk_pref[0] = total;
            __threadfence();
            atomicExch(&g_blk_state[0], 2);
        } else {
            g_blk_agg[b] = total;
            __threadfence();
            atomicExch(&g_blk_state[b], 1);
        }
    }
    if (wid == 0) {
        int excl = 0;
        if (b > 0) {
            int hi_end = b;                  // predecessors [0, b)
            while (hi_end > 0) {
                int start = hi_end - 32 > 0 ? hi_end - 32 : 0;
                int idx = start + lane;
                bool valid = (idx < hi_end);
                int st = 2;
                do {
                    if (valid) st = atomicAdd(&g_blk_state[idx], 0);
                } while (__any_sync(0xffffffffu, valid && st == 0));
                int val = 0;
                if (valid)
                    val = (st == 2) ? atomicAdd(&g_blk_pref[idx], 0)
                                    : atomicAdd(&g_blk_agg[idx], 0);
                unsigned m2 = __ballot_sync(0xffffffffu, valid && st == 2);
                int contrib;
                bool done;
                if (m2) {
                    int hi = 31 - __clz(m2);              // rightmost prefix-ready
                    contrib = (valid && lane >= hi) ? val : 0;
                    done = true;
                } else {
                    contrib = valid ? val : 0;
                    done = false;
                }
                #pragma unroll
                for (int dd = 16; dd > 0; dd >>= 1)
                    contrib += __shfl_down_sync(0xffffffffu, contrib, dd);
                excl += __shfl_sync(0xffffffffu, contrib, 0);
                if (done) break;
                hi_end = start;
            }
            if (lane == 0) {
                g_blk_pref[b] = excl + total;
                __threadfence();
                atomicExch(&g_blk_state[b], 2);
            }
        }
        if (lane == 0) s_excl = excl;
    }
    __syncthreads();

    if (inb) {
        int base = s_excl + thr_excl;
        int4 off = make_int4(base, base + t0, base + t1, base + t2);
        *reinterpret_cast<int4*>(&g_off[i4 * 4]) = off;
        *reinterpret_cast<int4*>(&g_cur[i4 * 4]) = off;
    }
}

// ---------------------------------------------------------------------------
// K3: bucket fill — 4 edges per thread, int4 loads
// ---------------------------------------------------------------------------
__global__ __launch_bounds__(256) void fill_kernel(const int* __restrict__ ei) {
    int t = blockIdx.x * blockDim.x + threadIdx.x;
    int base = t * 4;
    if (base >= NEDGES) return;
    int4 s = *reinterpret_cast<const int4*>(ei + base);
    int4 d = *reinterpret_cast<const int4*>(ei + NEDGES + base);
    int p0 = atomicAdd(&g_cur[d.x], 1);
    int p1 = atomicAdd(&g_cur[d.y], 1);
    int p2 = atomicAdd(&g_cur[d.z], 1);
    int p3 = atomicAdd(&g_cur[d.w], 1);
    g_srcs[p0] = s.x;
    g_srcs[p1] = s.y;
    g_srcs[p2] = s.z;
    g_srcs[p3] = s.w;
}

// ---------------------------------------------------------------------------
// K4: tf32 tensor-core GEMM  y[m,n] = sum_k x[m,k] * W[n,k] + b[n], fp16 out
// ---------------------------------------------------------------------------
#define GBM 128
#define GBK 16
#define SSTRIDE 136

__device__ __forceinline__ uint32_t f32_to_tf32(float f) {
    uint32_t r;
    asm("cvt.rna.tf32.f32 %0, %1;" : "=r"(r) : "f"(f));
    return r;
}

__global__ __launch_bounds__(256) void gemm_tf32_kernel(
    const float* __restrict__ x,
    const float* __restrict__ W,
    const float* __restrict__ b)
{
    __shared__ uint32_t As[GBK * SSTRIDE];
    __shared__ uint32_t Bs[GBK * SSTRIDE];

    const int tid  = threadIdx.x;
    const int lane = tid & 31;
    const int warp = tid >> 5;
    const int wm   = warp >> 1;
    const int wn   = warp & 1;
    const int block_m = blockIdx.x * GBM;
    const int grp = lane >> 2;
    const int qid = lane & 3;

    float acc[2][8][4];
    #pragma unroll
    for (int i = 0; i < 2; i++)
        #pragma unroll
        for (int j = 0; j < 8; j++)
            #pragma unroll
            for (int c = 0; c < 4; c++)
                acc[i][j][c] = 0.f;

    for (int k0 = 0; k0 < IN_C; k0 += GBK) {
        #pragma unroll
        for (int u = 0; u < 2; u++) {
            int idx = tid * 2 + u;
            int row = idx >> 2;
            int kq  = (idx & 3) * 4;

            float4 av = make_float4(0.f, 0.f, 0.f, 0.f);
            int gm = block_m + row;
            if (gm < NNODES)
                av = *reinterpret_cast<const float4*>(x + (size_t)gm * IN_C + k0 + kq);
            As[(kq + 0) * SSTRIDE + row] = f32_to_tf32(av.x);
            As[(kq + 1) * SSTRIDE + row] = f32_to_tf32(av.y);
            As[(kq + 2) * SSTRIDE + row] = f32_to_tf32(av.z);
            As[(kq + 3) * SSTRIDE + row] = f32_to_tf32(av.w);

            float4 bv = *reinterpret_cast<const float4*>(W + (size_t)row * IN_C + k0 + kq);
            Bs[(kq + 0) * SSTRIDE + row] = f32_to_tf32(bv.x);
            Bs[(kq + 1) * SSTRIDE + row] = f32_to_tf32(bv.y);
            Bs[(kq + 2) * SSTRIDE + row] = f32_to_tf32(bv.z);
            Bs[(kq + 3) * SSTRIDE + row] = f32_to_tf32(bv.w);
        }
        __syncthreads();

        #pragma unroll
        for (int s = 0; s < 2; s++) {
            const int kk = s * 8 + qid;

            uint32_t af[2][4];
            #pragma unroll
            for (int i = 0; i < 2; i++) {
                int rm = wm * 32 + i * 16 + grp;
                af[i][0] = As[kk * SSTRIDE + rm];
                af[i][1] = As[kk * SSTRIDE + rm + 8];
                af[i][2] = As[(kk + 4) * SSTRIDE + rm];
                af[i][3] = As[(kk + 4) * SSTRIDE + rm + 8];
            }
            uint32_t bf[8][2];
            #pragma unroll
            for (int j = 0; j < 8; j++) {
                int bn = wn * 64 + j * 8 + grp;
                bf[j][0] = Bs[kk * SSTRIDE + bn];
                bf[j][1] = Bs[(kk + 4) * SSTRIDE + bn];
            }
            #pragma unroll
            for (int i = 0; i < 2; i++)
                #pragma unroll
                for (int j = 0; j < 8; j++) {
                    asm volatile(
                        "mma.sync.aligned.m16n8k8.row.col.f32.tf32.tf32.f32 "
                        "{%0,%1,%2,%3}, {%4,%5,%6,%7}, {%8,%9}, {%0,%1,%2,%3};\n"
                        : "+f"(acc[i][j][0]), "+f"(acc[i][j][1]),
                          "+f"(acc[i][j][2]), "+f"(acc[i][j][3])
                        : "r"(af[i][0]), "r"(af[i][1]), "r"(af[i][2]), "r"(af[i][3]),
                          "r"(bf[j][0]), "r"(bf[j][1]));
                }
        }
        __syncthreads();
    }

    #pragma unroll
    for (int i = 0; i < 2; i++) {
        int r0 = block_m + wm * 32 + i * 16 + grp;
        int r1 = r0 + 8;
        #pragma unroll
        for (int j = 0; j < 8; j++) {
            int col = wn * 64 + j * 8 + qid * 2;
            float b0 = b[col], b1 = b[col + 1];
            if (r0 < NNODES) {
                __half2 h = __floats2half2_rn(acc[i][j][0] + b0, acc[i][j][1] + b1);
                *reinterpret_cast<__half2*>(&g_y[(size_t)r0 * OUT_C + col]) = h;
            }
            if (r1 < NNODES) {
                __half2 h = __floats2half2_rn(acc[i][j][2] + b0, acc[i][j][3] + b1);
                *reinterpret_cast<__half2*>(&g_y[(size_t)r1 * OUT_C + col]) = h;
            }
        }
    }
}

// ---------------------------------------------------------------------------
// K5: gather + mean. 2 nodes per warp; 16 lanes per node; one uint4 (8 halfs)
// per lane. fp32 accumulation, unrolled x8 for MLP.
// ---------------------------------------------------------------------------
__device__ __forceinline__ void acc_row(float* acc, uint4 v) {
    float2 f;
    f = __half22float2(*reinterpret_cast<__half2*>(&v.x)); acc[0] += f.x; acc[1] += f.y;
    f = __half22float2(*reinterpret_cast<__half2*>(&v.y)); acc[2] += f.x; acc[3] += f.y;
    f = __half22float2(*reinterpret_cast<__half2*>(&v.z)); acc[4] += f.x; acc[5] += f.y;
    f = __half22float2(*reinterpret_cast<__half2*>(&v.w)); acc[6] += f.x; acc[7] += f.y;
}

__global__ __launch_bounds__(256) void gather_kernel(float* __restrict__ out) {
    int warp_id = (blockIdx.x * blockDim.x + threadIdx.x) >> 5;
    int lane = threadIdx.x & 31;
    int half_id = lane >> 4;
    int sub = lane & 15;
    int node = warp_id * 2 + half_id;
    if (node >= NNODES) return;

    int s = g_off[node];
    int e = g_off[node + 1];

    float acc[8];
    #pragma unroll
    for (int c = 0; c < 8; c++) acc[c] = 0.f;

    const size_t loff = (size_t)sub * 8;

    int i = s;
    for (; i + 7 < e; i += 8) {
        int sn[8];
        #pragma unroll
        for (int q = 0; q < 8; q++) sn[q] = __ldg(&g_srcs[i + q]);
        uint4 v[8];
        #pragma unroll
        for (int q = 0; q < 8; q++)
            v[q] = *reinterpret_cast<const uint4*>(&g_y[(size_t)sn[q] * OUT_C + loff]);
        #pragma unroll
        for (int q = 0; q < 8; q++) acc_row(acc, v[q]);
    }
    for (; i + 3 < e; i += 4) {
        int sn[4];
        #pragma unroll
        for (int q = 0; q < 4; q++) sn[q] = __ldg(&g_srcs[i + q]);
        uint4 v[4];
        #pragma unroll
        for (int q = 0; q < 4; q++)
            v[q] = *reinterpret_cast<const uint4*>(&g_y[(size_t)sn[q] * OUT_C + loff]);
        #pragma unroll
        for (int q = 0; q < 4; q++) acc_row(acc, v[q]);
    }
    for (; i < e; i++) {
        int s0 = __ldg(&g_srcs[i]);
        uint4 v = *reinterpret_cast<const uint4*>(&g_y[(size_t)s0 * OUT_C + loff]);
        acc_row(acc, v);
    }

    float inv = 1.0f / (float)max(e - s, 1);
    float4 o0 = make_float4(acc[0] * inv, acc[1] * inv, acc[2] * inv, acc[3] * inv);
    float4 o1 = make_float4(acc[4] * inv, acc[5] * inv, acc[6] * inv, acc[7] * inv);
    float* op = out + (size_t)node * OUT_C + loff;
    *reinterpret_cast<float4*>(op) = o0;
    *reinterpret_cast<float4*>(op + 4) = o1;
}

// ---------------------------------------------------------------------------
extern "C" void kernel_launch(void* const* d_in, const int* in_sizes, int n_in,
                              void* d_out, int out_size) {
    const float* x  = (const float*)d_in[0];
    const int*   ei = (const int*)d_in[1];
    const float* W  = (const float*)d_in[2];
    const float* b  = (const float*)d_in[3];
    float* out = (float*)d_out;

    static cudaStream_t s_gemm = nullptr;
    static cudaEvent_t ev_fork = nullptr, ev_join = nullptr;
    if (!s_gemm) {
        cudaStreamCreateWithFlags(&s_gemm, cudaStreamNonBlocking);
        cudaEventCreateWithFlags(&ev_fork, cudaEventDisableTiming);
        cudaEventCreateWithFlags(&ev_join, cudaEventDisableTiming);
    }

    int edge_blocks = (NEDGES / 4 + 255) / 256;

    // Fork: GEMM on side stream (independent of CSR build)
    cudaEventRecord(ev_fork, 0);
    cudaStreamWaitEvent(s_gemm, ev_fork, 0);
    gemm_tf32_kernel<<<(NNODES + GBM - 1) / GBM, 256, 0, s_gemm>>>(x, W, b);
    cudaEventRecord(ev_join, s_gemm);

    // CSR build on main stream
    zero_deg_kernel<<<NB2, 256>>>();
    hist_kernel<<<edge_blocks, 256>>>(ei);
    scan_lookback_kernel<<<NB2, 256>>>();
    fill_kernel<<<edge_blocks, 256>>>(ei);

    // Join, then gather + mean
    cudaStreamWaitEvent(0, ev_join, 0);
    gather_kernel<<<(NNODES / 2 * 32 + 255) / 256, 256>>>(out);
}